// round 4
// baseline (speedup 1.0000x reference)
#include <cuda_runtime.h>
#include <cuda_fp16.h>
#include <cstdint>

#define BATCH 4096
#define IN_C 1024
#define OUT_C 1024
#define KDIM 8192   // IN_C * 8

// Scratch (static device globals — allocation-free per harness rules)
static __device__ __align__(1024) __half g_basis[(size_t)BATCH * KDIM]; // 64 MB
static __device__ __align__(1024) __half g_coef[(size_t)OUT_C * KDIM];  // 16 MB

__device__ __forceinline__ uint32_t smem_u32(const void* p) {
    uint32_t a;
    asm("{ .reg .u64 t; cvta.to.shared.u64 t, %1; cvt.u32.u64 %0, t; }"
        : "=r"(a) : "l"(p));
    return a;
}

// ---------------------------------------------------------------------------
// Kernel 1: basis[b, i*8+m] = sigmoid(2*slope*(u - c)),  u = alpha*x + beta
// ---------------------------------------------------------------------------
__global__ void k_basis(const float* __restrict__ x, const float* __restrict__ centers,
                        const float* __restrict__ slopes, const float* __restrict__ alpha,
                        const float* __restrict__ beta) {
    int idx = blockIdx.x * blockDim.x + threadIdx.x;  // b * IN_C + i
    int i = idx & (IN_C - 1);
    float u = fmaf(alpha[i], x[idx], beta[i]);
    float4 c0 = reinterpret_cast<const float4*>(centers)[2 * i];
    float4 c1 = reinterpret_cast<const float4*>(centers)[2 * i + 1];
    float4 s0 = reinterpret_cast<const float4*>(slopes)[2 * i];
    float4 s1 = reinterpret_cast<const float4*>(slopes)[2 * i + 1];
    float cc[8] = {c0.x, c0.y, c0.z, c0.w, c1.x, c1.y, c1.z, c1.w};
    float ss[8] = {s0.x, s0.y, s0.z, s0.w, s1.x, s1.y, s1.z, s1.w};
    union { __half h[8]; uint4 v; } out;
#pragma unroll
    for (int m = 0; m < 8; m++) {
        // 0.5*(1+tanh(z)) == sigmoid(2z); exp overflow/underflow saturate correctly.
        float e = __expf(-2.0f * ss[m] * (u - cc[m]));
        out.h[m] = __float2half_rn(__fdividef(1.0f, 1.0f + e));
    }
    reinterpret_cast<uint4*>(g_basis)[idx] = out.v;
}

// ---------------------------------------------------------------------------
// Kernel 2: coeffs fp32 -> fp16 (layout [o, i*8+m] is already K-major)
// ---------------------------------------------------------------------------
__global__ void k_conv(const float* __restrict__ c) {
    int idx = blockIdx.x * blockDim.x + threadIdx.x;  // per 4 floats
    float4 v = reinterpret_cast<const float4*>(c)[idx];
    union { __half2 h2[2]; uint2 u; } o;
    o.h2[0] = __floats2half2_rn(v.x, v.y);
    o.h2[1] = __floats2half2_rn(v.z, v.w);
    reinterpret_cast<uint2*>(g_coef)[idx] = o.u;
}

// ---------------------------------------------------------------------------
// Kernel 3: HMMA fp16 GEMM  y[4096,1024] = basis @ coef^T
// mma.sync m16n8k16 (family-common PTX), BM=BN=128, BK=64,
// 4-stage cp.async pipeline, XOR-swizzled smem + ldmatrix.x4.
// ---------------------------------------------------------------------------
#define BM 128
#define BN 128
#define BK 64
#define STAGES 4
#define NTHR 256
#define NCHUNK (KDIM / BK)          // 128

#define T_BYTES (BM * 128)          // 16 KB per operand tile (128B row = 64 fp16)
#define STG_BYTES (2 * T_BYTES)     // 32 KB
#define SM_TOTAL (STAGES * STG_BYTES)  // 128 KB

__device__ __forceinline__ void cp16(uint32_t dst, const void* src) {
    asm volatile("cp.async.cg.shared.global [%0], [%1], 16;" :: "r"(dst), "l"(src));
}
__device__ __forceinline__ void ldm_x4(uint32_t& r0, uint32_t& r1, uint32_t& r2, uint32_t& r3, uint32_t addr) {
    asm volatile("ldmatrix.sync.aligned.m8n8.x4.shared.b16 {%0,%1,%2,%3}, [%4];"
                 : "=r"(r0), "=r"(r1), "=r"(r2), "=r"(r3) : "r"(addr));
}
__device__ __forceinline__ void mma16816(float* d, const uint32_t* a, const uint32_t* b) {
    asm volatile("mma.sync.aligned.m16n8k16.row.col.f32.f16.f16.f32 "
                 "{%0,%1,%2,%3}, {%4,%5,%6,%7}, {%8,%9}, {%0,%1,%2,%3};"
                 : "+f"(d[0]), "+f"(d[1]), "+f"(d[2]), "+f"(d[3])
                 : "r"(a[0]), "r"(a[1]), "r"(a[2]), "r"(a[3]), "r"(b[0]), "r"(b[1]));
}

// Smem tile layout: row r (0..127) x 128 bytes (= BK halves).
// Physical offset = r*128 + (c16*16 ^ ((r&7)<<4)), conflict-free for both
// cp.async stores and ldmatrix reads.
__device__ __forceinline__ void load_stage(uint32_t sb, int stage,
                                           const __half* Ag, const __half* Bg,
                                           int chunk, int tid) {
    uint32_t sA = sb + stage * STG_BYTES;
    uint32_t sB = sA + T_BYTES;
    const char* gA = (const char*)Ag + (size_t)chunk * (BK * 2);
    const char* gB = (const char*)Bg + (size_t)chunk * (BK * 2);
#pragma unroll
    for (int j = 0; j < (T_BYTES / 16) / NTHR; j++) {   // 4 iters per operand
        int seg = tid + j * NTHR;                       // row = seg>>3, c16 = seg&7
        uint32_t row = (uint32_t)seg >> 3;
        uint32_t off = row * 128u + ((((uint32_t)seg & 7u) * 16u) ^ ((row & 7u) << 4));
        size_t gofs = (size_t)row * (KDIM * 2) + (size_t)((seg & 7) << 4);
        cp16(sA + off, gA + gofs);
        cp16(sB + off, gB + gofs);
    }
}

__global__ void __launch_bounds__(NTHR, 1)
k_gemm(float* __restrict__ y) {
    extern __shared__ char smem[];
    uint32_t sb = smem_u32(smem);
    int tid = threadIdx.x;
    int wid = tid >> 5, lid = tid & 31;
    int tn = blockIdx.x, tm = blockIdx.y;
    const __half* Ag = g_basis + (size_t)tm * BM * KDIM;
    const __half* Bg = g_coef + (size_t)tn * BN * KDIM;

    int wm = wid >> 1;          // 0..3 -> warp rows wm*32
    int wn = wid & 1;           // 0..1 -> warp cols wn*64

    // A fragment addressing: mt in {0,1}
    uint32_t aRow[2], aXor[2];
#pragma unroll
    for (int mt = 0; mt < 2; mt++) {
        aRow[mt] = (uint32_t)(wm * 32 + mt * 16 + (lid & 15));
        aXor[mt] = (aRow[mt] & 7u) << 4;
    }
    uint32_t aCol = (uint32_t)((lid >> 4) * 16);

    // B fragment addressing: p in 0..3 (each covers n16 = two n8 tiles)
    uint32_t bRow[4], bXor[4];
#pragma unroll
    for (int p = 0; p < 4; p++) {
        bRow[p] = (uint32_t)(wn * 64 + p * 16 + ((lid >> 4) << 3) + (lid & 7));
        bXor[p] = (bRow[p] & 7u) << 4;
    }
    uint32_t bCol = (uint32_t)(((lid >> 3) & 1) * 16);

    float acc[2][8][4];
#pragma unroll
    for (int mt = 0; mt < 2; mt++)
#pragma unroll
        for (int nt = 0; nt < 8; nt++)
#pragma unroll
            for (int q = 0; q < 4; q++) acc[mt][nt][q] = 0.0f;

    // Prologue: stages 0..STAGES-2
#pragma unroll
    for (int s = 0; s < STAGES - 1; s++) {
        load_stage(sb, s, Ag, Bg, s, tid);
        asm volatile("cp.async.commit_group;" ::: "memory");
    }

    uint32_t afr[2][2][4];   // [buf][mt][4]
    uint32_t bfr[2][4][4];   // [buf][p][4]

#pragma unroll 1
    for (int c = 0; c < NCHUNK; c++) {
        asm volatile("cp.async.wait_group %0;" :: "n"(STAGES - 2) : "memory");
        __syncthreads();
        // Refill stage (c-1)&3 with chunk c+STAGES-1; all warps finished reading
        // stage c-1 before this barrier.
        int nc = c + STAGES - 1;
        if (nc < NCHUNK) load_stage(sb, nc & (STAGES - 1), Ag, Bg, nc, tid);
        asm volatile("cp.async.commit_group;" ::: "memory");

        uint32_t sA = sb + (uint32_t)(c & (STAGES - 1)) * STG_BYTES;
        uint32_t sB = sA + T_BYTES;

        // kk = 0 fragments
#pragma unroll
        for (int mt = 0; mt < 2; mt++)
            ldm_x4(afr[0][mt][0], afr[0][mt][1], afr[0][mt][2], afr[0][mt][3],
                   sA + aRow[mt] * 128u + (aCol ^ aXor[mt]));
#pragma unroll
        for (int p = 0; p < 4; p++)
            ldm_x4(bfr[0][p][0], bfr[0][p][1], bfr[0][p][2], bfr[0][p][3],
                   sB + bRow[p] * 128u + (bCol ^ bXor[p]));

#pragma unroll
        for (int kk = 0; kk < 4; kk++) {
            int cur = kk & 1, nxt = cur ^ 1;
            if (kk < 3) {
                uint32_t koff = (uint32_t)(kk + 1) * 32u;
#pragma unroll
                for (int mt = 0; mt < 2; mt++)
                    ldm_x4(afr[nxt][mt][0], afr[nxt][mt][1], afr[nxt][mt][2], afr[nxt][mt][3],
                           sA + aRow[mt] * 128u + ((koff + aCol) ^ aXor[mt]));
#pragma unroll
                for (int p = 0; p < 4; p++)
                    ldm_x4(bfr[nxt][p][0], bfr[nxt][p][1], bfr[nxt][p][2], bfr[nxt][p][3],
                           sB + bRow[p] * 128u + ((koff + bCol) ^ bXor[p]));
            }
#pragma unroll
            for (int mt = 0; mt < 2; mt++)
#pragma unroll
                for (int p = 0; p < 4; p++) {
                    mma16816(acc[mt][2 * p + 0], afr[cur][mt], &bfr[cur][p][0]);
                    mma16816(acc[mt][2 * p + 1], afr[cur][mt], &bfr[cur][p][2]);
                }
        }
    }
    asm volatile("cp.async.wait_group 0;" ::: "memory");

    // Epilogue: direct float2 stores
    int r0 = wm * 32 + (lid >> 2);
    int cb = wn * 64 + (lid & 3) * 2;
#pragma unroll
    for (int mt = 0; mt < 2; mt++) {
#pragma unroll
        for (int nt = 0; nt < 8; nt++) {
            int row = tm * BM + r0 + mt * 16;
            int col = tn * BN + cb + nt * 8;
            float2 v0 = make_float2(acc[mt][nt][0], acc[mt][nt][1]);
            float2 v1 = make_float2(acc[mt][nt][2], acc[mt][nt][3]);
            *reinterpret_cast<float2*>(y + (size_t)row * OUT_C + col) = v0;
            *reinterpret_cast<float2*>(y + (size_t)(row + 8) * OUT_C + col) = v1;
        }
    }
}

// ---------------------------------------------------------------------------
extern "C" void kernel_launch(void* const* d_in, const int* in_sizes, int n_in,
                              void* d_out, int out_size) {
    (void)in_sizes; (void)n_in; (void)out_size;
    const float* x       = (const float*)d_in[0];
    const float* coeffs  = (const float*)d_in[1];
    const float* centers = (const float*)d_in[2];
    const float* slopes  = (const float*)d_in[3];
    const float* alpha   = (const float*)d_in[4];
    const float* beta    = (const float*)d_in[5];
    float* y = (float*)d_out;

    k_basis<<<(BATCH * IN_C) / 256, 256>>>(x, centers, slopes, alpha, beta);
    k_conv<<<(OUT_C * KDIM / 4) / 256, 256>>>(coeffs);
    cudaFuncSetAttribute(k_gemm, cudaFuncAttributeMaxDynamicSharedMemorySize, SM_TOTAL);
    k_gemm<<<dim3(OUT_C / BN, BATCH / BM), NTHR, SM_TOTAL>>>(y);
}

// round 5
// speedup vs baseline: 1.1108x; 1.1108x over previous
#include <cuda_runtime.h>
#include <cuda_fp16.h>
#include <cstdint>

#define BATCH 4096
#define IN_C 1024
#define OUT_C 1024
#define KDIM 8192   // IN_C * 8

// Scratch (static device globals — allocation-free per harness rules)
static __device__ __align__(1024) __half g_basis[(size_t)BATCH * KDIM]; // 64 MB
static __device__ __align__(1024) __half g_coef[(size_t)OUT_C * KDIM];  // 16 MB
static __device__ __align__(1024) float  g_E[IN_C * 8];                 // exp(2*s*c) table

__device__ __forceinline__ uint32_t smem_u32(const void* p) {
    uint32_t a;
    asm("{ .reg .u64 t; cvta.to.shared.u64 t, %1; cvt.u32.u64 %0, t; }"
        : "=r"(a) : "l"(p));
    return a;
}

// ---------------------------------------------------------------------------
// Kernel 0: E[i,m] = exp(2*slope*center)   (8192 values)
// ---------------------------------------------------------------------------
__global__ void k_etab(const float* __restrict__ centers, const float* __restrict__ slopes) {
    int j = blockIdx.x * blockDim.x + threadIdx.x;
    g_E[j] = __expf(2.0f * slopes[j] * centers[j]);
}

// ---------------------------------------------------------------------------
// Kernel 1: basis[b, i*8+m] = sigmoid(2*slope*(u - c)),  u = alpha*x + beta
// Factored: e_m = exp(-2*s*u) * E[i,m]  (slopes uniform across m per spec)
// ---------------------------------------------------------------------------
__global__ void k_basis(const float* __restrict__ x, const float* __restrict__ slopes,
                        const float* __restrict__ alpha, const float* __restrict__ beta) {
    int idx = blockIdx.x * blockDim.x + threadIdx.x;  // b * IN_C + i
    int i = idx & (IN_C - 1);
    float u = fmaf(alpha[i], x[idx], beta[i]);
    float s = slopes[8 * i];
    float t = __expf(-2.0f * s * u);
    float4 e0 = reinterpret_cast<const float4*>(g_E)[2 * i];
    float4 e1 = reinterpret_cast<const float4*>(g_E)[2 * i + 1];
    float ee[8] = {e0.x, e0.y, e0.z, e0.w, e1.x, e1.y, e1.z, e1.w};
    union { __half h[8]; uint4 v; } out;
#pragma unroll
    for (int m = 0; m < 8; m++) {
        float e = t * ee[m];                 // overflow->inf->sig 0; underflow->0->sig 1 (both correct)
        out.h[m] = __float2half_rn(__fdividef(1.0f, 1.0f + e));
    }
    reinterpret_cast<uint4*>(g_basis)[idx] = out.v;
}

// ---------------------------------------------------------------------------
// Kernel 2: coeffs fp32 -> fp16 (layout [o, i*8+m] is already K-major)
// ---------------------------------------------------------------------------
__global__ void k_conv(const float* __restrict__ c) {
    int idx = blockIdx.x * blockDim.x + threadIdx.x;  // per 4 floats
    float4 v = reinterpret_cast<const float4*>(c)[idx];
    union { __half2 h2[2]; uint2 u; } o;
    o.h2[0] = __floats2half2_rn(v.x, v.y);
    o.h2[1] = __floats2half2_rn(v.z, v.w);
    reinterpret_cast<uint2*>(g_coef)[idx] = o.u;
}

// ---------------------------------------------------------------------------
// Kernel 3: HMMA fp16 GEMM  y[4096,1024] = basis @ coef^T
// mma.sync m16n8k16, BM=128, BN=256, BK=64, 64x64 warp tiles (8 warps),
// 3-stage cp.async pipeline, XOR-swizzled smem + ldmatrix.x4.
// Grid 4x32 = 128 CTAs = single wave.
// ---------------------------------------------------------------------------
#define BM 128
#define BN 256
#define BK 64
#define STAGES 3
#define NTHR 256
#define NCHUNK (KDIM / BK)          // 128

#define A_BYTES (BM * 128)          // 16 KB  (128B row = 64 fp16 = BK)
#define B_BYTES (BN * 128)          // 32 KB
#define STG_BYTES (A_BYTES + B_BYTES)      // 48 KB
#define SM_TOTAL (STAGES * STG_BYTES)      // 144 KB

__device__ __forceinline__ void cp16(uint32_t dst, const void* src) {
    asm volatile("cp.async.cg.shared.global [%0], [%1], 16;" :: "r"(dst), "l"(src));
}
__device__ __forceinline__ void ldm_x4(uint32_t& r0, uint32_t& r1, uint32_t& r2, uint32_t& r3, uint32_t addr) {
    asm volatile("ldmatrix.sync.aligned.m8n8.x4.shared.b16 {%0,%1,%2,%3}, [%4];"
                 : "=r"(r0), "=r"(r1), "=r"(r2), "=r"(r3) : "r"(addr));
}
__device__ __forceinline__ void mma16816(float* d, const uint32_t* a, const uint32_t* b) {
    asm volatile("mma.sync.aligned.m16n8k16.row.col.f32.f16.f16.f32 "
                 "{%0,%1,%2,%3}, {%4,%5,%6,%7}, {%8,%9}, {%0,%1,%2,%3};"
                 : "+f"(d[0]), "+f"(d[1]), "+f"(d[2]), "+f"(d[3])
                 : "r"(a[0]), "r"(a[1]), "r"(a[2]), "r"(a[3]), "r"(b[0]), "r"(b[1]));
}

// Smem tile layout: row r x 128 bytes; physical = r*128 + (c16*16 ^ ((r&7)<<4))
__device__ __forceinline__ void load_stage(uint32_t sb, int stage,
                                           const __half* Ag, const __half* Bg,
                                           int chunk, int tid) {
    uint32_t sA = sb + stage * STG_BYTES;
    uint32_t sB = sA + A_BYTES;
    const char* gA = (const char*)Ag + (size_t)chunk * (BK * 2);
    const char* gB = (const char*)Bg + (size_t)chunk * (BK * 2);
#pragma unroll
    for (int j = 0; j < (A_BYTES / 16) / NTHR; j++) {   // 4 iters
        int seg = tid + j * NTHR;                       // row = seg>>3, c16 = seg&7
        uint32_t row = (uint32_t)seg >> 3;
        uint32_t off = row * 128u + ((((uint32_t)seg & 7u) * 16u) ^ ((row & 7u) << 4));
        cp16(sA + off, gA + (size_t)row * (KDIM * 2) + (size_t)((seg & 7) << 4));
    }
#pragma unroll
    for (int j = 0; j < (B_BYTES / 16) / NTHR; j++) {   // 8 iters
        int seg = tid + j * NTHR;
        uint32_t row = (uint32_t)seg >> 3;
        uint32_t off = row * 128u + ((((uint32_t)seg & 7u) * 16u) ^ ((row & 7u) << 4));
        cp16(sB + off, gB + (size_t)row * (KDIM * 2) + (size_t)((seg & 7) << 4));
    }
}

__global__ void __launch_bounds__(NTHR, 1)
k_gemm(float* __restrict__ y) {
    extern __shared__ char smem[];
    uint32_t sb = smem_u32(smem);
    int tid = threadIdx.x;
    int wid = tid >> 5, lid = tid & 31;
    int tn = blockIdx.x, tm = blockIdx.y;
    const __half* Ag = g_basis + (size_t)tm * BM * KDIM;
    const __half* Bg = g_coef + (size_t)tn * BN * KDIM;

    int wm = wid >> 2;          // 0..1 -> warp rows wm*64
    int wn = wid & 3;           // 0..3 -> warp cols wn*64

    // A fragments: mt 0..3 (m16 each)
    uint32_t aRow[4], aXor[4];
#pragma unroll
    for (int mt = 0; mt < 4; mt++) {
        aRow[mt] = (uint32_t)(wm * 64 + mt * 16 + (lid & 15));
        aXor[mt] = (aRow[mt] & 7u) << 4;
    }
    uint32_t aCol = (uint32_t)((lid >> 4) * 16);

    // B fragments: p 0..3 (n16 each -> two n8 tiles)
    uint32_t bRow[4], bXor[4];
#pragma unroll
    for (int p = 0; p < 4; p++) {
        bRow[p] = (uint32_t)(wn * 64 + p * 16 + ((lid >> 4) << 3) + (lid & 7));
        bXor[p] = (bRow[p] & 7u) << 4;
    }
    uint32_t bCol = (uint32_t)(((lid >> 3) & 1) * 16);

    float acc[4][8][4];
#pragma unroll
    for (int mt = 0; mt < 4; mt++)
#pragma unroll
        for (int nt = 0; nt < 8; nt++)
#pragma unroll
            for (int q = 0; q < 4; q++) acc[mt][nt][q] = 0.0f;

    // Prologue: stages 0..STAGES-2
#pragma unroll
    for (int s = 0; s < STAGES - 1; s++) {
        load_stage(sb, s, Ag, Bg, s, tid);
        asm volatile("cp.async.commit_group;" ::: "memory");
    }

    uint32_t afr[4][4];   // [mt][4]
    uint32_t bfr[4][4];   // [p][4]

#pragma unroll 1
    for (int c = 0; c < NCHUNK; c++) {
        asm volatile("cp.async.wait_group %0;" :: "n"(STAGES - 2) : "memory");
        __syncthreads();
        // Refill stage used by chunk c-1 (all warps finished it before this barrier)
        int nc = c + STAGES - 1;
        if (nc < NCHUNK) load_stage(sb, nc % STAGES, Ag, Bg, nc, tid);
        asm volatile("cp.async.commit_group;" ::: "memory");

        uint32_t sA = sb + (uint32_t)(c % STAGES) * STG_BYTES;
        uint32_t sB = sA + A_BYTES;

#pragma unroll
        for (int kk = 0; kk < 4; kk++) {
            uint32_t koff = (uint32_t)kk * 32u;
#pragma unroll
            for (int mt = 0; mt < 4; mt++)
                ldm_x4(afr[mt][0], afr[mt][1], afr[mt][2], afr[mt][3],
                       sA + aRow[mt] * 128u + ((koff + aCol) ^ aXor[mt]));
#pragma unroll
            for (int p = 0; p < 4; p++)
                ldm_x4(bfr[p][0], bfr[p][1], bfr[p][2], bfr[p][3],
                       sB + bRow[p] * 128u + ((koff + bCol) ^ bXor[p]));
#pragma unroll
            for (int mt = 0; mt < 4; mt++)
#pragma unroll
                for (int p = 0; p < 4; p++) {
                    mma16816(acc[mt][2 * p + 0], afr[mt], &bfr[p][0]);
                    mma16816(acc[mt][2 * p + 1], afr[mt], &bfr[p][2]);
                }
        }
    }
    asm volatile("cp.async.wait_group 0;" ::: "memory");

    // Epilogue: direct float2 stores
    int r0 = wm * 64 + (lid >> 2);
    int cb = wn * 64 + (lid & 3) * 2;
#pragma unroll
    for (int mt = 0; mt < 4; mt++) {
#pragma unroll
        for (int nt = 0; nt < 8; nt++) {
            int row = tm * BM + r0 + mt * 16;
            int col = tn * BN + cb + nt * 8;
            float2 v0 = make_float2(acc[mt][nt][0], acc[mt][nt][1]);
            float2 v1 = make_float2(acc[mt][nt][2], acc[mt][nt][3]);
            *reinterpret_cast<float2*>(y + (size_t)row * OUT_C + col) = v0;
            *reinterpret_cast<float2*>(y + (size_t)(row + 8) * OUT_C + col) = v1;
        }
    }
}

// ---------------------------------------------------------------------------
extern "C" void kernel_launch(void* const* d_in, const int* in_sizes, int n_in,
                              void* d_out, int out_size) {
    (void)in_sizes; (void)n_in; (void)out_size;
    const float* x       = (const float*)d_in[0];
    const float* coeffs  = (const float*)d_in[1];
    const float* centers = (const float*)d_in[2];
    const float* slopes  = (const float*)d_in[3];
    const float* alpha   = (const float*)d_in[4];
    const float* beta    = (const float*)d_in[5];
    float* y = (float*)d_out;

    k_etab<<<(IN_C * 8) / 256, 256>>>(centers, slopes);
    k_basis<<<(BATCH * IN_C) / 256, 256>>>(x, slopes, alpha, beta);
    k_conv<<<(OUT_C * KDIM / 4) / 256, 256>>>(coeffs);
    cudaFuncSetAttribute(k_gemm, cudaFuncAttributeMaxDynamicSharedMemorySize, SM_TOTAL);
    k_gemm<<<dim3(OUT_C / BN, BATCH / BM), NTHR, SM_TOTAL>>>(y);
}

// round 7
// speedup vs baseline: 1.1355x; 1.0223x over previous
#include <cuda_runtime.h>
#include <cuda_fp16.h>
#include <cstdint>

#define BATCH 4096
#define IN_C 1024
#define OUT_C 1024
#define KDIM 8192   // IN_C * 8

// Scratch (static device globals — allocation-free per harness rules)
static __device__ __align__(1024) __half g_basis[(size_t)BATCH * KDIM]; // 64 MB
static __device__ __align__(1024) __half g_coef[(size_t)OUT_C * KDIM];  // 16 MB
static __device__ __align__(1024) float  g_E[IN_C * 8];                 // exp(2*s*c) table

__device__ __forceinline__ uint32_t smem_u32(const void* p) {
    uint32_t a;
    asm("{ .reg .u64 t; cvta.to.shared.u64 t, %1; cvt.u32.u64 %0, t; }"
        : "=r"(a) : "l"(p));
    return a;
}

// ---------------------------------------------------------------------------
// Kernel 0: E[i,m] = exp(2*slope*center)   (8192 values)
// ---------------------------------------------------------------------------
__global__ void k_etab(const float* __restrict__ centers, const float* __restrict__ slopes) {
    int j = blockIdx.x * blockDim.x + threadIdx.x;
    g_E[j] = __expf(2.0f * slopes[j] * centers[j]);
}

// ---------------------------------------------------------------------------
// Kernel 1: basis[b, i*8+m] = sigmoid(2*slope*(u - c)),  u = alpha*x + beta
// Factored: e_m = exp(-2*s*u) * E[i,m]  (slopes uniform across m per spec)
// ---------------------------------------------------------------------------
__global__ void k_basis(const float* __restrict__ x, const float* __restrict__ slopes,
                        const float* __restrict__ alpha, const float* __restrict__ beta) {
    int idx = blockIdx.x * blockDim.x + threadIdx.x;  // b * IN_C + i
    int i = idx & (IN_C - 1);
    float u = fmaf(alpha[i], x[idx], beta[i]);
    float s = slopes[8 * i];
    float t = __expf(-2.0f * s * u);
    float4 e0 = reinterpret_cast<const float4*>(g_E)[2 * i];
    float4 e1 = reinterpret_cast<const float4*>(g_E)[2 * i + 1];
    float ee[8] = {e0.x, e0.y, e0.z, e0.w, e1.x, e1.y, e1.z, e1.w};
    union { __half h[8]; uint4 v; } out;
#pragma unroll
    for (int m = 0; m < 8; m++) {
        float e = t * ee[m];                 // overflow->inf->sig 0; underflow->0->sig 1 (both correct)
        out.h[m] = __float2half_rn(__fdividef(1.0f, 1.0f + e));
    }
    reinterpret_cast<uint4*>(g_basis)[idx] = out.v;
}

// ---------------------------------------------------------------------------
// Kernel 2: coeffs fp32 -> fp16 (layout [o, i*8+m] is already K-major)
// ---------------------------------------------------------------------------
__global__ void k_conv(const float* __restrict__ c) {
    int idx = blockIdx.x * blockDim.x + threadIdx.x;  // per 4 floats
    float4 v = reinterpret_cast<const float4*>(c)[idx];
    union { __half2 h2[2]; uint2 u; } o;
    o.h2[0] = __floats2half2_rn(v.x, v.y);
    o.h2[1] = __floats2half2_rn(v.z, v.w);
    reinterpret_cast<uint2*>(g_coef)[idx] = o.u;
}

// ---------------------------------------------------------------------------
// Kernel 3: HMMA fp16 GEMM  y[4096,1024] = basis @ coef^T
// mma.sync m16n8k16, BM=128, BN=256, BK=64, 64x32 warp tiles (16 warps),
// 3-stage cp.async pipeline, XOR-swizzled smem + ldmatrix.x4,
// fragment double-buffering across k-steps. Grid 4x32 = 128 CTAs, one wave.
// ---------------------------------------------------------------------------
#define BM 128
#define BN 256
#define BK 64
#define STAGES 3
#define NTHR 512
#define NCHUNK (KDIM / BK)          // 128

#define A_BYTES (BM * 128)          // 16 KB  (128B row = 64 fp16 = BK)
#define B_BYTES (BN * 128)          // 32 KB
#define STG_BYTES (A_BYTES + B_BYTES)      // 48 KB
#define SM_TOTAL (STAGES * STG_BYTES)      // 144 KB

__device__ __forceinline__ void cp16(uint32_t dst, const void* src) {
    asm volatile("cp.async.cg.shared.global [%0], [%1], 16;" :: "r"(dst), "l"(src));
}
__device__ __forceinline__ void ldm_x4(uint32_t& r0, uint32_t& r1, uint32_t& r2, uint32_t& r3, uint32_t addr) {
    asm volatile("ldmatrix.sync.aligned.m8n8.x4.shared.b16 {%0,%1,%2,%3}, [%4];"
                 : "=r"(r0), "=r"(r1), "=r"(r2), "=r"(r3) : "r"(addr));
}
__device__ __forceinline__ void mma16816(float* d, const uint32_t* a, const uint32_t* b) {
    asm volatile("mma.sync.aligned.m16n8k16.row.col.f32.f16.f16.f32 "
                 "{%0,%1,%2,%3}, {%4,%5,%6,%7}, {%8,%9}, {%0,%1,%2,%3};"
                 : "+f"(d[0]), "+f"(d[1]), "+f"(d[2]), "+f"(d[3])
                 : "r"(a[0]), "r"(a[1]), "r"(a[2]), "r"(a[3]), "r"(b[0]), "r"(b[1]));
}

// Smem tile layout: row r x 128 bytes; physical = r*128 + (c16*16 ^ ((r&7)<<4))
__device__ __forceinline__ void load_stage(uint32_t sb, int stage,
                                           const __half* Ag, const __half* Bg,
                                           int chunk, int tid) {
    uint32_t sA = sb + stage * STG_BYTES;
    uint32_t sB = sA + A_BYTES;
    const char* gA = (const char*)Ag + (size_t)chunk * (BK * 2);
    const char* gB = (const char*)Bg + (size_t)chunk * (BK * 2);
#pragma unroll
    for (int j = 0; j < (A_BYTES / 16) / NTHR; j++) {   // 2 iters
        int seg = tid + j * NTHR;                       // row = seg>>3, c16 = seg&7
        uint32_t row = (uint32_t)seg >> 3;
        uint32_t off = row * 128u + ((((uint32_t)seg & 7u) * 16u) ^ ((row & 7u) << 4));
        cp16(sA + off, gA + (size_t)row * (KDIM * 2) + (size_t)((seg & 7) << 4));
    }
#pragma unroll
    for (int j = 0; j < (B_BYTES / 16) / NTHR; j++) {   // 4 iters
        int seg = tid + j * NTHR;
        uint32_t row = (uint32_t)seg >> 3;
        uint32_t off = row * 128u + ((((uint32_t)seg & 7u) * 16u) ^ ((row & 7u) << 4));
        cp16(sB + off, gB + (size_t)row * (KDIM * 2) + (size_t)((seg & 7) << 4));
    }
}

__global__ void __launch_bounds__(NTHR, 1)
k_gemm(float* __restrict__ y) {
    extern __shared__ char smem[];
    uint32_t sb = smem_u32(smem);
    int tid = threadIdx.x;
    int wid = tid >> 5, lid = tid & 31;
    int tn = blockIdx.x, tm = blockIdx.y;
    const __half* Ag = g_basis + (size_t)tm * BM * KDIM;
    const __half* Bg = g_coef + (size_t)tn * BN * KDIM;

    int wm = wid >> 3;          // 0..1 -> warp rows wm*64
    int wn = wid & 7;           // 0..7 -> warp cols wn*32

    // A fragments: mt 0..3 (m16 each)
    uint32_t aRow[4], aXor[4];
#pragma unroll
    for (int mt = 0; mt < 4; mt++) {
        aRow[mt] = (uint32_t)(wm * 64 + mt * 16 + (lid & 15));
        aXor[mt] = (aRow[mt] & 7u) << 4;
    }
    uint32_t aCol = (uint32_t)((lid >> 4) * 16);

    // B fragments: p 0..1 (n16 each -> two n8 tiles)
    uint32_t bRow[2], bXor[2];
#pragma unroll
    for (int p = 0; p < 2; p++) {
        bRow[p] = (uint32_t)(wn * 32 + p * 16 + ((lid >> 4) << 3) + (lid & 7));
        bXor[p] = (bRow[p] & 7u) << 4;
    }
    uint32_t bCol = (uint32_t)(((lid >> 3) & 1) * 16);

    float acc[4][4][4];
#pragma unroll
    for (int mt = 0; mt < 4; mt++)
#pragma unroll
        for (int nt = 0; nt < 4; nt++)
#pragma unroll
            for (int q = 0; q < 4; q++) acc[mt][nt][q] = 0.0f;

    // Prologue: stages 0..STAGES-2
#pragma unroll
    for (int s = 0; s < STAGES - 1; s++) {
        load_stage(sb, s, Ag, Bg, s, tid);
        asm volatile("cp.async.commit_group;" ::: "memory");
    }

    uint32_t afr[2][4][4];   // [buf][mt][4]
    uint32_t bfr[2][2][4];   // [buf][p][4]

#pragma unroll 1
    for (int c = 0; c < NCHUNK; c++) {
        asm volatile("cp.async.wait_group %0;" :: "n"(STAGES - 2) : "memory");
        __syncthreads();
        // Refill stage used by chunk c-1 (all warps finished it before this barrier)
        int nc = c + STAGES - 1;
        if (nc < NCHUNK) load_stage(sb, nc % STAGES, Ag, Bg, nc, tid);
        asm volatile("cp.async.commit_group;" ::: "memory");

        uint32_t sA = sb + (uint32_t)(c % STAGES) * STG_BYTES;
        uint32_t sB = sA + A_BYTES;

        // kk = 0 fragments into buf 0
#pragma unroll
        for (int mt = 0; mt < 4; mt++)
            ldm_x4(afr[0][mt][0], afr[0][mt][1], afr[0][mt][2], afr[0][mt][3],
                   sA + aRow[mt] * 128u + (aCol ^ aXor[mt]));
#pragma unroll
        for (int p = 0; p < 2; p++)
            ldm_x4(bfr[0][p][0], bfr[0][p][1], bfr[0][p][2], bfr[0][p][3],
                   sB + bRow[p] * 128u + (bCol ^ bXor[p]));

#pragma unroll
        for (int kk = 0; kk < 4; kk++) {
            int cur = kk & 1, nxt = cur ^ 1;
            if (kk < 3) {
                uint32_t koff = (uint32_t)(kk + 1) * 32u;
#pragma unroll
                for (int mt = 0; mt < 4; mt++)
                    ldm_x4(afr[nxt][mt][0], afr[nxt][mt][1], afr[nxt][mt][2], afr[nxt][mt][3],
                           sA + aRow[mt] * 128u + ((koff + aCol) ^ aXor[mt]));
#pragma unroll
                for (int p = 0; p < 2; p++)
                    ldm_x4(bfr[nxt][p][0], bfr[nxt][p][1], bfr[nxt][p][2], bfr[nxt][p][3],
                           sB + bRow[p] * 128u + ((koff + bCol) ^ bXor[p]));
            }
#pragma unroll
            for (int mt = 0; mt < 4; mt++)
#pragma unroll
                for (int p = 0; p < 2; p++) {
                    mma16816(acc[mt][2 * p + 0], afr[cur][mt], &bfr[cur][p][0]);
                    mma16816(acc[mt][2 * p + 1], afr[cur][mt], &bfr[cur][p][2]);
                }
        }
    }
    asm volatile("cp.async.wait_group 0;" ::: "memory");

    // Epilogue: direct float2 stores
    int r0 = wm * 64 + (lid >> 2);
    int cb = wn * 32 + (lid & 3) * 2;
#pragma unroll
    for (int mt = 0; mt < 4; mt++) {
#pragma unroll
        for (int nt = 0; nt < 4; nt++) {
            int row = tm * BM + r0 + mt * 16;
            int col = tn * BN + cb + nt * 8;
            float2 v0 = make_float2(acc[mt][nt][0], acc[mt][nt][1]);
            float2 v1 = make_float2(acc[mt][nt][2], acc[mt][nt][3]);
            *reinterpret_cast<float2*>(y + (size_t)row * OUT_C + col) = v0;
            *reinterpret_cast<float2*>(y + (size_t)(row + 8) * OUT_C + col) = v1;
        }
    }
}

// ---------------------------------------------------------------------------
extern "C" void kernel_launch(void* const* d_in, const int* in_sizes, int n_in,
                              void* d_out, int out_size) {
    (void)in_sizes; (void)n_in; (void)out_size;
    const float* x       = (const float*)d_in[0];
    const float* coeffs  = (const float*)d_in[1];
    const float* centers = (const float*)d_in[2];
    const float* slopes  = (const float*)d_in[3];
    const float* alpha   = (const float*)d_in[4];
    const float* beta    = (const float*)d_in[5];
    float* y = (float*)d_out;

    k_etab<<<(IN_C * 8) / 256, 256>>>(centers, slopes);
    k_basis<<<(BATCH * IN_C) / 256, 256>>>(x, slopes, alpha, beta);
    k_conv<<<(OUT_C * KDIM / 4) / 256, 256>>>(coeffs);
    cudaFuncSetAttribute(k_gemm, cudaFuncAttributeMaxDynamicSharedMemorySize, SM_TOTAL);
    k_gemm<<<dim3(OUT_C / BN, BATCH / BM), NTHR, SM_TOTAL>>>(y);
}